// round 3
// baseline (speedup 1.0000x reference)
#include <cuda_runtime.h>

typedef unsigned long long u64;

#define BATCH 8
#define DIM   64
#define TLEN  16384
#define INNER 128
#define TT    128
#define NTILES (TLEN/TT)
#define TTO   256
#define NTILES_O (TLEN/TTO)
#define LOG2E 1.4426950408889634f

// Scratch (device globals; no runtime allocation)
__device__ float g_E[(size_t)BATCH*INNER*TLEN];   // 64 MB: exp(qraw)
__device__ float g_qsum[BATCH*INNER];
__device__ float g_ksum[BATCH*INNER];
__device__ float g_xsum[BATCH*DIM];
__device__ float g_A[BATCH*64*INNER];

// ---- packed fp32x2 helpers (Blackwell) ----
__device__ __forceinline__ u64 pack2(float lo, float hi) {
    u64 r; asm("mov.b64 %0, {%1,%2};" : "=l"(r) : "f"(lo), "f"(hi)); return r;
}
__device__ __forceinline__ float2 unpack2(u64 v) {
    float lo, hi; asm("mov.b64 {%0,%1}, %2;" : "=f"(lo), "=f"(hi) : "l"(v));
    return make_float2(lo, hi);
}
__device__ __forceinline__ void fma2(u64 &d, u64 a, u64 b) {
    asm("fma.rn.f32x2 %0, %1, %2, %0;" : "+l"(d) : "l"(a), "l"(b));
}
__device__ __forceinline__ u64 add2(u64 a, u64 b) {
    u64 r; asm("add.rn.f32x2 %0, %1, %2;" : "=l"(r) : "l"(a), "l"(b)); return r;
}
__device__ __forceinline__ float ex2(float x) {
    float r; asm("ex2.approx.f32 %0, %1;" : "=f"(r) : "f"(x)); return r;
}
__device__ __forceinline__ float rcpa(float x) {
    float r; asm("rcp.approx.f32 %0, %1;" : "=f"(r) : "f"(x)); return r;
}

__global__ void k_zero() {
    int i = blockIdx.x*blockDim.x + threadIdx.x;
    if (i < BATCH*INNER) { g_qsum[i] = 0.f; g_ksum[i] = 0.f; }
    if (i < BATCH*DIM)   { g_xsum[i] = 0.f; }
}

// 128(c) x 128(t) tile GEMM, W pre-duplicated as f32x2 pairs in ws2.
// acc[j][p] holds t-pair (tx*8+2p, +1) for channel ty*8+j.
__device__ __forceinline__ void mm_tile2(const float* __restrict__ xs,
                                         const u64* __restrict__ ws2,
                                         int tx, int ty, u64 acc[8][4]) {
    #pragma unroll 8
    for (int kk = 0; kk < DIM; kk++) {
        ulonglong2 xa = *(const ulonglong2*)&xs[kk*TT + tx*8];
        ulonglong2 xb = *(const ulonglong2*)&xs[kk*TT + tx*8 + 4];
        ulonglong2 w01 = *(const ulonglong2*)&ws2[kk*INNER + ty*8];
        ulonglong2 w23 = *(const ulonglong2*)&ws2[kk*INNER + ty*8 + 2];
        ulonglong2 w45 = *(const ulonglong2*)&ws2[kk*INNER + ty*8 + 4];
        ulonglong2 w67 = *(const ulonglong2*)&ws2[kk*INNER + ty*8 + 6];
        u64 wv[8] = {w01.x, w01.y, w23.x, w23.y, w45.x, w45.y, w67.x, w67.y};
        #pragma unroll
        for (int j = 0; j < 8; j++) {
            fma2(acc[j][0], wv[j], xa.x);
            fma2(acc[j][1], wv[j], xa.y);
            fma2(acc[j][2], wv[j], xb.x);
            fma2(acc[j][3], wv[j], xb.y);
        }
    }
}

// Pass 1: per (b, t-tile): qraw -> exp2 -> E + qsum ; kraw -> per-t head softmax -> ksum ; xsum
__global__ void __launch_bounds__(256) k_reduce(const float* __restrict__ x,
                                                const float* __restrict__ wqkv) {
    extern __shared__ float sm[];
    u64*   ws2 = (u64*)sm;                       // [64][128] u64   64 KB
    float* xs  = sm + 2*DIM*INNER;               // [64][TT]        32 KB
    float* red = xs + DIM*TT;                    // [16][TT]         8 KB
    const int b   = blockIdx.y;
    const int t0  = blockIdx.x * TT;
    const int tid = threadIdx.x;
    const int tx  = tid & 15;   // t subtile (8 consecutive t each)
    const int ty  = tid >> 4;   // c subtile (8 consecutive c each)

    const float* xb = x + (size_t)b*DIM*TLEN + t0;
    for (int idx = tid; idx < DIM*TT; idx += 256) {
        int kk = idx >> 7, t = idx & (TT-1);
        xs[idx] = xb[(size_t)kk*TLEN + t];
    }
    // Wq transposed, *log2e, duplicated to f32x2 pairs
    for (int idx = tid; idx < DIM*INNER; idx += 256) {
        int c = idx >> 6, kk = idx & 63;
        float w = wqkv[idx] * LOG2E;
        ws2[kk*INNER + c] = pack2(w, w);
    }
    __syncthreads();

    if (tid < DIM) {
        float s = 0.f;
        #pragma unroll 8
        for (int t = 0; t < TT; t++) s += xs[tid*TT + t];
        atomicAdd(&g_xsum[b*DIM + tid], s);
    }

    u64 acc[8][4];
    #pragma unroll
    for (int j = 0; j < 8; j++)
        #pragma unroll
        for (int p = 0; p < 4; p++) acc[j][p] = 0ull;

    // ---- Phase A: qraw ----
    mm_tile2(xs, ws2, tx, ty, acc);

    #pragma unroll
    for (int j = 0; j < 8; j++) {
        int c = ty*8 + j;
        float e[8]; float s = 0.f;
        #pragma unroll
        for (int p = 0; p < 4; p++) {
            float2 v = unpack2(acc[j][p]);
            e[2*p]   = ex2(v.x);
            e[2*p+1] = ex2(v.y);
            s += e[2*p] + e[2*p+1];
        }
        #pragma unroll
        for (int off = 8; off > 0; off >>= 1)
            s += __shfl_down_sync(0xffffffffu, s, off, 16);
        if (tx == 0) atomicAdd(&g_qsum[b*INNER + c], s);
        ulonglong2 s0, s1;
        s0.x = pack2(e[0], e[1]); s0.y = pack2(e[2], e[3]);
        s1.x = pack2(e[4], e[5]); s1.y = pack2(e[6], e[7]);
        ulonglong2* ep = (ulonglong2*)&g_E[((size_t)b*INNER + c)*TLEN + t0 + tx*8];
        ep[0] = s0; ep[1] = s1;
    }
    __syncthreads();   // all Wq reads done

    // Wk transposed, *log2e, duplicated
    for (int idx = tid; idx < DIM*INNER; idx += 256) {
        int c = idx >> 6, kk = idx & 63;
        float w = wqkv[INNER*DIM + idx] * LOG2E;
        ws2[kk*INNER + c] = pack2(w, w);
    }
    __syncthreads();

    #pragma unroll
    for (int j = 0; j < 8; j++)
        #pragma unroll
        for (int p = 0; p < 4; p++) acc[j][p] = 0ull;

    // ---- Phase B: kraw ----
    mm_tile2(xs, ws2, tx, ty, acc);

    // exp2 + per-t partial sums (packed over t pairs)
    u64 pt2[4] = {0ull, 0ull, 0ull, 0ull};
    #pragma unroll
    for (int j = 0; j < 8; j++)
        #pragma unroll
        for (int p = 0; p < 4; p++) {
            float2 v = unpack2(acc[j][p]);
            u64 e2 = pack2(ex2(v.x), ex2(v.y));
            acc[j][p] = e2;
            pt2[p] = add2(pt2[p], e2);
        }
    #pragma unroll
    for (int p = 0; p < 4; p++)
        *(u64*)&red[ty*TT + tx*8 + 2*p] = pt2[p];
    __syncthreads();

    // head sums over d (32 channels = 4 consecutive ty rows) -> 1/hs, then ksum
    const int rbase = (ty & ~3)*TT + tx*8;
    u64 inv2[4];
    #pragma unroll
    for (int p = 0; p < 4; p++) {
        u64 h = add2(add2(*(const u64*)&red[rbase + 2*p],
                          *(const u64*)&red[rbase + TT + 2*p]),
                     add2(*(const u64*)&red[rbase + 2*TT + 2*p],
                          *(const u64*)&red[rbase + 3*TT + 2*p]));
        float2 hf = unpack2(h);
        inv2[p] = pack2(rcpa(hf.x), rcpa(hf.y));
    }
    #pragma unroll
    for (int j = 0; j < 8; j++) {
        u64 s2 = 0ull;
        #pragma unroll
        for (int p = 0; p < 4; p++) fma2(s2, acc[j][p], inv2[p]);
        float2 v = unpack2(s2);
        float s = v.x + v.y;
        #pragma unroll
        for (int off = 8; off > 0; off >>= 1)
            s += __shfl_down_sync(0xffffffffu, s, off, 16);
        if (tx == 0) atomicAdd(&g_ksum[b*INNER + ty*8 + j], s);
    }
}

// Pass 2 (tiny): vsum = Wv @ xsum ; A[b][o][c] = w_out[o][c] * ksum*vsum/qsum
__global__ void k_scale(const float* __restrict__ wqkv,
                        const float* __restrict__ wout) {
    int b = blockIdx.x, c = threadIdx.x;   // 128 threads
    __shared__ float ss[INNER];
    float vs = 0.f;
    const float* wv = wqkv + (size_t)(2*INNER + c)*DIM;
    #pragma unroll
    for (int kk = 0; kk < DIM; kk++) vs += wv[kk] * g_xsum[b*DIM + kk];
    ss[c] = g_ksum[b*INNER + c] * vs / g_qsum[b*INNER + c];
    __syncthreads();
    for (int idx = c; idx < 64*INNER; idx += 128) {
        int cc = idx & 127;
        g_A[b*64*INNER + idx] = wout[idx] * ss[cc];
    }
}

// Pass 3: y[b,o,t] = sum_c A[b,o,c] * E[b,c,t] + b_out[o]
// 256t x 64o tile; thread = 8t x 8o; A staged as duplicated f32x2 pairs.
__global__ void __launch_bounds__(256) k_out(const float* __restrict__ bout,
                                             float* __restrict__ y) {
    extern __shared__ float sm[];
    float* Es  = sm;                          // [INNER][TTO] 128 KB
    u64*   As2 = (u64*)(sm + INNER*TTO);      // [INNER][64] u64 64 KB
    float* bo  = (float*)(As2 + INNER*64);    // [64]
    const int b   = blockIdx.y;
    const int t0  = blockIdx.x * TTO;
    const int tid = threadIdx.x;
    const int tx  = tid & 31;    // 8 t each -> 256 t
    const int ty  = tid >> 5;    // 8 o each -> 64 o

    for (int idx = tid; idx < INNER*TTO; idx += 256)
        Es[idx] = g_E[((size_t)b*INNER + (idx >> 8))*TLEN + t0 + (idx & 255)];
    for (int idx = tid; idx < 64*INNER; idx += 256) {
        int o = idx >> 7, c = idx & 127;
        float a = g_A[b*64*INNER + idx];
        As2[c*64 + o] = pack2(a, a);
    }
    if (tid < 64) bo[tid] = bout[tid];
    __syncthreads();

    u64 acc[8][4];
    #pragma unroll
    for (int j = 0; j < 8; j++)
        #pragma unroll
        for (int p = 0; p < 4; p++) acc[j][p] = 0ull;

    #pragma unroll 8
    for (int c = 0; c < INNER; c++) {
        ulonglong2 ea = *(const ulonglong2*)&Es[c*TTO + tx*8];
        ulonglong2 eb = *(const ulonglong2*)&Es[c*TTO + tx*8 + 4];
        ulonglong2 a01 = *(const ulonglong2*)&As2[c*64 + ty*8];
        ulonglong2 a23 = *(const ulonglong2*)&As2[c*64 + ty*8 + 2];
        ulonglong2 a45 = *(const ulonglong2*)&As2[c*64 + ty*8 + 4];
        ulonglong2 a67 = *(const ulonglong2*)&As2[c*64 + ty*8 + 6];
        u64 av[8] = {a01.x, a01.y, a23.x, a23.y, a45.x, a45.y, a67.x, a67.y};
        #pragma unroll
        for (int j = 0; j < 8; j++) {
            fma2(acc[j][0], av[j], ea.x);
            fma2(acc[j][1], av[j], ea.y);
            fma2(acc[j][2], av[j], eb.x);
            fma2(acc[j][3], av[j], eb.y);
        }
    }

    #pragma unroll
    for (int j = 0; j < 8; j++) {
        int o = ty*8 + j;
        u64 bb = pack2(bo[o], bo[o]);
        ulonglong2 r0, r1;
        r0.x = add2(acc[j][0], bb); r0.y = add2(acc[j][1], bb);
        r1.x = add2(acc[j][2], bb); r1.y = add2(acc[j][3], bb);
        ulonglong2* yp = (ulonglong2*)&y[((size_t)b*64 + o)*TLEN + t0 + tx*8];
        yp[0] = r0; yp[1] = r1;
    }
}

#define SMEM_REDUCE ((2*DIM*INNER + DIM*TT + 16*TT)*4)        /* 106496 */
#define SMEM_OUT    ((INNER*TTO + 2*INNER*64 + 64)*4)         /* 196864 */

extern "C" void kernel_launch(void* const* d_in, const int* in_sizes, int n_in,
                              void* d_out, int out_size) {
    const float* x    = (const float*)d_in[0];
    const float* wqkv = (const float*)d_in[1];
    const float* wout = (const float*)d_in[2];
    const float* bout = (const float*)d_in[3];
    float* y = (float*)d_out;

    cudaFuncSetAttribute((const void*)k_reduce,
                         cudaFuncAttributeMaxDynamicSharedMemorySize, SMEM_REDUCE);
    cudaFuncSetAttribute((const void*)k_out,
                         cudaFuncAttributeMaxDynamicSharedMemorySize, SMEM_OUT);

    k_zero<<<4, 256>>>();
    dim3 g(NTILES, BATCH);
    k_reduce<<<g, 256, SMEM_REDUCE>>>(x, wqkv);
    k_scale<<<BATCH, 128>>>(wqkv, wout);
    dim3 go(NTILES_O, BATCH);
    k_out<<<go, 256, SMEM_OUT>>>(bout, y);
}

// round 4
// speedup vs baseline: 1.3296x; 1.3296x over previous
#include <cuda_runtime.h>

typedef unsigned long long u64;

#define BATCH 8
#define DIM   64
#define TLEN  16384
#define INNER 128
#define TT    128
#define NTILES (TLEN/TT)
#define TTO   256
#define NTILES_O (TLEN/TTO)
#define LOG2E 1.4426950408889634f

// Scratch (device globals; no runtime allocation)
__device__ float g_E[(size_t)BATCH*INNER*TLEN];   // 64 MB: exp(qraw)
__device__ float g_qsum[BATCH*INNER];
__device__ float g_ksum[BATCH*INNER];
__device__ float g_xsum[BATCH*DIM];
__device__ float g_A[BATCH*64*INNER];

// ---- packed fp32x2 helpers (Blackwell) ----
__device__ __forceinline__ u64 pack2(float lo, float hi) {
    u64 r; asm("mov.b64 %0, {%1,%2};" : "=l"(r) : "f"(lo), "f"(hi)); return r;
}
__device__ __forceinline__ float2 unpack2(u64 v) {
    float lo, hi; asm("mov.b64 {%0,%1}, %2;" : "=f"(lo), "=f"(hi) : "l"(v));
    return make_float2(lo, hi);
}
__device__ __forceinline__ void fma2(u64 &d, u64 a, u64 b) {
    asm("fma.rn.f32x2 %0, %1, %2, %0;" : "+l"(d) : "l"(a), "l"(b));
}
__device__ __forceinline__ u64 add2(u64 a, u64 b) {
    u64 r; asm("add.rn.f32x2 %0, %1, %2;" : "=l"(r) : "l"(a), "l"(b)); return r;
}
__device__ __forceinline__ float ex2(float x) {
    float r; asm("ex2.approx.f32 %0, %1;" : "=f"(r) : "f"(x)); return r;
}
__device__ __forceinline__ float rcpa(float x) {
    float r; asm("rcp.approx.f32 %0, %1;" : "=f"(r) : "f"(x)); return r;
}

__global__ void k_zero() {
    int i = blockIdx.x*blockDim.x + threadIdx.x;
    if (i < BATCH*INNER) { g_qsum[i] = 0.f; g_ksum[i] = 0.f; }
    if (i < BATCH*DIM)   { g_xsum[i] = 0.f; }
}

// 128(c) x 128(t) tile GEMM, W pre-duplicated as f32x2 pairs in ws2.
// Thread's 8 t's = {tx*4..+3} and {64+tx*4..+3}  (conflict-free LDS.128).
// acc[j][0..1] = t-pairs of first quad, acc[j][2..3] = second quad, channel ty*8+j.
__device__ __forceinline__ void mm_tile2(const float* __restrict__ xs,
                                         const u64* __restrict__ ws2,
                                         int tx, int ty, u64 acc[8][4]) {
    #pragma unroll 8
    for (int kk = 0; kk < DIM; kk++) {
        ulonglong2 xa = *(const ulonglong2*)&xs[kk*TT + tx*4];
        ulonglong2 xb = *(const ulonglong2*)&xs[kk*TT + 64 + tx*4];
        ulonglong2 w01 = *(const ulonglong2*)&ws2[kk*INNER + ty*8];
        ulonglong2 w23 = *(const ulonglong2*)&ws2[kk*INNER + ty*8 + 2];
        ulonglong2 w45 = *(const ulonglong2*)&ws2[kk*INNER + ty*8 + 4];
        ulonglong2 w67 = *(const ulonglong2*)&ws2[kk*INNER + ty*8 + 6];
        u64 wv[8] = {w01.x, w01.y, w23.x, w23.y, w45.x, w45.y, w67.x, w67.y};
        #pragma unroll
        for (int j = 0; j < 8; j++) {
            fma2(acc[j][0], wv[j], xa.x);
            fma2(acc[j][1], wv[j], xa.y);
            fma2(acc[j][2], wv[j], xb.x);
            fma2(acc[j][3], wv[j], xb.y);
        }
    }
}

// Pass 1: per (b, t-tile): qraw -> exp2 -> E + qsum ; kraw -> per-t head softmax -> ksum ; xsum
__global__ void __launch_bounds__(256) k_reduce(const float* __restrict__ x,
                                                const float* __restrict__ wqkv) {
    extern __shared__ float sm[];
    u64*   ws2 = (u64*)sm;                       // [64][128] u64   64 KB
    float* xs  = sm + 2*DIM*INNER;               // [64][TT]        32 KB
    float* red = xs + DIM*TT;                    // [16][TT]         8 KB
    const int b   = blockIdx.y;
    const int t0  = blockIdx.x * TT;
    const int tid = threadIdx.x;
    const int tx  = tid & 15;   // t quads at tx*4 and 64+tx*4
    const int ty  = tid >> 4;   // c subtile (8 consecutive c each)

    const float* xb = x + (size_t)b*DIM*TLEN + t0;
    for (int idx = tid; idx < DIM*TT; idx += 256) {
        int kk = idx >> 7, t = idx & (TT-1);
        xs[idx] = xb[(size_t)kk*TLEN + t];
    }
    // Wq transposed, *log2e, duplicated to f32x2 pairs
    for (int idx = tid; idx < DIM*INNER; idx += 256) {
        int c = idx >> 6, kk = idx & 63;
        float w = wqkv[idx] * LOG2E;
        ws2[kk*INNER + c] = pack2(w, w);
    }
    __syncthreads();

    if (tid < DIM) {
        float s = 0.f;
        #pragma unroll 8
        for (int t = 0; t < TT; t++) s += xs[tid*TT + t];
        atomicAdd(&g_xsum[b*DIM + tid], s);
    }

    u64 acc[8][4];
    #pragma unroll
    for (int j = 0; j < 8; j++)
        #pragma unroll
        for (int p = 0; p < 4; p++) acc[j][p] = 0ull;

    // ---- Phase A: qraw ----
    mm_tile2(xs, ws2, tx, ty, acc);

    #pragma unroll
    for (int j = 0; j < 8; j++) {
        int c = ty*8 + j;
        float e[8]; float s = 0.f;
        #pragma unroll
        for (int p = 0; p < 4; p++) {
            float2 v = unpack2(acc[j][p]);
            e[2*p]   = ex2(v.x);
            e[2*p+1] = ex2(v.y);
            s += e[2*p] + e[2*p+1];
        }
        #pragma unroll
        for (int off = 8; off > 0; off >>= 1)
            s += __shfl_down_sync(0xffffffffu, s, off, 16);
        if (tx == 0) atomicAdd(&g_qsum[b*INNER + c], s);
        float* eb0 = &g_E[((size_t)b*INNER + c)*TLEN + t0];
        *(float4*)&eb0[tx*4]      = make_float4(e[0], e[1], e[2], e[3]);
        *(float4*)&eb0[64 + tx*4] = make_float4(e[4], e[5], e[6], e[7]);
    }
    __syncthreads();   // all Wq reads done

    // Wk transposed, *log2e, duplicated
    for (int idx = tid; idx < DIM*INNER; idx += 256) {
        int c = idx >> 6, kk = idx & 63;
        float w = wqkv[INNER*DIM + idx] * LOG2E;
        ws2[kk*INNER + c] = pack2(w, w);
    }
    __syncthreads();

    #pragma unroll
    for (int j = 0; j < 8; j++)
        #pragma unroll
        for (int p = 0; p < 4; p++) acc[j][p] = 0ull;

    // ---- Phase B: kraw ----
    mm_tile2(xs, ws2, tx, ty, acc);

    // exp2 + per-t partial sums (packed over t pairs)
    u64 pt2[4] = {0ull, 0ull, 0ull, 0ull};
    #pragma unroll
    for (int j = 0; j < 8; j++)
        #pragma unroll
        for (int p = 0; p < 4; p++) {
            float2 v = unpack2(acc[j][p]);
            u64 e2 = pack2(ex2(v.x), ex2(v.y));
            acc[j][p] = e2;
            pt2[p] = add2(pt2[p], e2);
        }
    // t offsets for p: 0->tx*4, 1->tx*4+2, 2->64+tx*4, 3->64+tx*4+2
    *(u64*)&red[ty*TT + tx*4]          = pt2[0];
    *(u64*)&red[ty*TT + tx*4 + 2]      = pt2[1];
    *(u64*)&red[ty*TT + 64 + tx*4]     = pt2[2];
    *(u64*)&red[ty*TT + 64 + tx*4 + 2] = pt2[3];
    __syncthreads();

    // head sums over d (32 channels = 4 consecutive ty rows) -> 1/hs, then ksum
    const int rb = (ty & ~3)*TT;
    const int toff[4] = {tx*4, tx*4 + 2, 64 + tx*4, 64 + tx*4 + 2};
    u64 inv2[4];
    #pragma unroll
    for (int p = 0; p < 4; p++) {
        int o = rb + toff[p];
        u64 h = add2(add2(*(const u64*)&red[o],
                          *(const u64*)&red[o + TT]),
                     add2(*(const u64*)&red[o + 2*TT],
                          *(const u64*)&red[o + 3*TT]));
        float2 hf = unpack2(h);
        inv2[p] = pack2(rcpa(hf.x), rcpa(hf.y));
    }
    #pragma unroll
    for (int j = 0; j < 8; j++) {
        u64 s2 = 0ull;
        #pragma unroll
        for (int p = 0; p < 4; p++) fma2(s2, acc[j][p], inv2[p]);
        float2 v = unpack2(s2);
        float s = v.x + v.y;
        #pragma unroll
        for (int off = 8; off > 0; off >>= 1)
            s += __shfl_down_sync(0xffffffffu, s, off, 16);
        if (tx == 0) atomicAdd(&g_ksum[b*INNER + ty*8 + j], s);
    }
}

// Pass 2 (tiny): vsum = Wv @ xsum ; A[b][o][c] = w_out[o][c] * ksum*vsum/qsum
__global__ void k_scale(const float* __restrict__ wqkv,
                        const float* __restrict__ wout) {
    int b = blockIdx.x, c = threadIdx.x;   // 128 threads
    __shared__ float ss[INNER];
    float vs = 0.f;
    const float* wv = wqkv + (size_t)(2*INNER + c)*DIM;
    #pragma unroll
    for (int kk = 0; kk < DIM; kk++) vs += wv[kk] * g_xsum[b*DIM + kk];
    ss[c] = g_ksum[b*INNER + c] * vs / g_qsum[b*INNER + c];
    __syncthreads();
    for (int idx = c; idx < 64*INNER; idx += 128) {
        int cc = idx & 127;
        g_A[b*64*INNER + idx] = wout[idx] * ss[cc];
    }
}

// Pass 3: y[b,o,t] = sum_c A[b,o,c] * E[b,c,t] + b_out[o]
// 256t x 64o tile per block, c streamed through smem in 2 halves of 64.
// Thread: 8t ({tx*4..+3} and {128+tx*4..+3}) x 8o (ty*8..+7). Conflict-free LDS.
__global__ void __launch_bounds__(256) k_out(const float* __restrict__ bout,
                                             float* __restrict__ y) {
    extern __shared__ float sm[];
    float* Es = sm;                      // [64][TTO]  64 KB (one c-half)
    float* As = sm + 64*TTO;             // [128][64]  32 KB (c-major, o inner)
    float* bo = As + INNER*64;           // [64]
    const int b   = blockIdx.y;
    const int t0  = blockIdx.x * TTO;
    const int tid = threadIdx.x;
    const int tx  = tid & 31;    // t quads at tx*4 and 128+tx*4
    const int ty  = tid >> 5;    // 8 o each -> 64 o

    for (int idx = tid; idx < 64*INNER; idx += 256) {
        int o = idx >> 7, c = idx & 127;
        As[c*64 + o] = g_A[b*64*INNER + idx];
    }
    if (tid < 64) bo[tid] = bout[tid];

    u64 acc[8][4];
    #pragma unroll
    for (int j = 0; j < 8; j++)
        #pragma unroll
        for (int p = 0; p < 4; p++) acc[j][p] = 0ull;

    #pragma unroll
    for (int h = 0; h < 2; h++) {
        const int c0 = h*64;
        __syncthreads();   // (h=0: also covers As/bo fill) Es free to overwrite
        for (int idx = tid; idx < 64*TTO; idx += 256)
            Es[idx] = g_E[((size_t)b*INNER + c0 + (idx >> 8))*TLEN + t0 + (idx & 255)];
        __syncthreads();

        #pragma unroll 8
        for (int cc = 0; cc < 64; cc++) {
            ulonglong2 ea = *(const ulonglong2*)&Es[cc*TTO + tx*4];
            ulonglong2 eb = *(const ulonglong2*)&Es[cc*TTO + 128 + tx*4];
            float4 a0 = *(const float4*)&As[(c0 + cc)*64 + ty*8];
            float4 a1 = *(const float4*)&As[(c0 + cc)*64 + ty*8 + 4];
            float af[8] = {a0.x,a0.y,a0.z,a0.w,a1.x,a1.y,a1.z,a1.w};
            #pragma unroll
            for (int j = 0; j < 8; j++) {
                u64 ad = pack2(af[j], af[j]);
                fma2(acc[j][0], ad, ea.x);
                fma2(acc[j][1], ad, ea.y);
                fma2(acc[j][2], ad, eb.x);
                fma2(acc[j][3], ad, eb.y);
            }
        }
    }

    #pragma unroll
    for (int j = 0; j < 8; j++) {
        int o = ty*8 + j;
        u64 bb = pack2(bo[o], bo[o]);
        ulonglong2 r0, r1;
        r0.x = add2(acc[j][0], bb); r0.y = add2(acc[j][1], bb);
        r1.x = add2(acc[j][2], bb); r1.y = add2(acc[j][3], bb);
        float* yb = &y[((size_t)b*64 + o)*TLEN + t0];
        *(ulonglong2*)&yb[tx*4]       = r0;
        *(ulonglong2*)&yb[128 + tx*4] = r1;
    }
}

#define SMEM_REDUCE ((2*DIM*INNER + DIM*TT + 16*TT)*4)   /* 106496 */
#define SMEM_OUT    ((64*TTO + INNER*64 + 64)*4)         /*  98560 */

extern "C" void kernel_launch(void* const* d_in, const int* in_sizes, int n_in,
                              void* d_out, int out_size) {
    const float* x    = (const float*)d_in[0];
    const float* wqkv = (const float*)d_in[1];
    const float* wout = (const float*)d_in[2];
    const float* bout = (const float*)d_in[3];
    float* y = (float*)d_out;

    cudaFuncSetAttribute((const void*)k_reduce,
                         cudaFuncAttributeMaxDynamicSharedMemorySize, SMEM_REDUCE);
    cudaFuncSetAttribute((const void*)k_out,
                         cudaFuncAttributeMaxDynamicSharedMemorySize, SMEM_OUT);

    k_zero<<<4, 256>>>();
    dim3 g(NTILES, BATCH);
    k_reduce<<<g, 256, SMEM_REDUCE>>>(x, wqkv);
    k_scale<<<BATCH, 128>>>(wqkv, wout);
    dim3 go(NTILES_O, BATCH);
    k_out<<<go, 256, SMEM_OUT>>>(bout, y);
}